// round 12
// baseline (speedup 1.0000x reference)
#include <cuda_runtime.h>
#include <math.h>

#define BATCH 2
#define SEQ 2048
#define DM 1024
#define OD 1024
#define NH 16
#define HD 64
#define MR (BATCH*SEQ)   // 4096
#define LOG2E 1.4426950408889634f

// Projection outputs (tf32-rounded fp32; Q pre-scaled by log2e/8): [B*SEQ][OD]
__device__ float g_qw[MR*OD];
__device__ float g_kw[MR*OD];
__device__ float g_vw[MR*OD];
// Pre-converted weights (tf32-rounded) and softmax bias (log2 domain)
__device__ float g_wc[3*DM*OD];
__device__ float g_bias[MR];

// ---------------------------------------------------------------------------
// helpers
// ---------------------------------------------------------------------------
__device__ __forceinline__ unsigned ftf(float x) {
    unsigned r; asm("cvt.rna.tf32.f32 %0, %1;" : "=r"(r) : "f"(x)); return r;
}
__device__ __forceinline__ float ftff(float x) {
    return __uint_as_float(ftf(x));
}
__device__ __forceinline__ float ex2(float x) {
    float r; asm("ex2.approx.f32 %0, %1;" : "=f"(r) : "f"(x)); return r;
}
__device__ __forceinline__ unsigned smem_u32(const void* p) {
    unsigned a;
    asm("{ .reg .u64 t; cvta.to.shared.u64 t, %1; cvt.u32.u64 %0, t; }"
        : "=r"(a) : "l"(p));
    return a;
}
__device__ __forceinline__ void cpa16(unsigned dst, const void* src) {
    asm volatile("cp.async.cg.shared.global [%0], [%1], 16;"
                 :: "r"(dst), "l"(src) : "memory");
}
#define CP_COMMIT() asm volatile("cp.async.commit_group;" ::: "memory")
#define CP_WAIT0()  asm volatile("cp.async.wait_group 0;" ::: "memory")

// D += A(16x8,row) * B(8x8,col)  tf32, fp32 accum
__device__ __forceinline__ void mma8(float* d, const unsigned* a, const unsigned* b) {
    asm volatile(
        "mma.sync.aligned.m16n8k8.row.col.f32.tf32.tf32.f32 "
        "{%0,%1,%2,%3}, {%4,%5,%6,%7}, {%8,%9}, {%0,%1,%2,%3};"
        : "+f"(d[0]), "+f"(d[1]), "+f"(d[2]), "+f"(d[3])
        : "r"(a[0]), "r"(a[1]), "r"(a[2]), "r"(a[3]), "r"(b[0]), "r"(b[1]));
}
// ldmatrix x4 on 32-bit words
__device__ __forceinline__ void ldsm4(unsigned* r, unsigned addr) {
    asm volatile("ldmatrix.sync.aligned.m8n8.x4.shared.b16 {%0,%1,%2,%3}, [%4];"
        : "=r"(r[0]), "=r"(r[1]), "=r"(r[2]), "=r"(r[3]) : "r"(addr));
}
// ldmatrix x2
__device__ __forceinline__ void ldsm2(unsigned* r, unsigned addr) {
    asm volatile("ldmatrix.sync.aligned.m8n8.x2.shared.b16 {%0,%1}, [%2];"
        : "=r"(r[0]), "=r"(r[1]) : "r"(addr));
}

// ===========================================================================
// Prepass: round weights to tf32; precompute log2-domain softmax bias.
// ===========================================================================
__global__ __launch_bounds__(256) void prepass(
    const float* __restrict__ wq, const float* __restrict__ wk,
    const float* __restrict__ wv, const float* __restrict__ vmask)
{
    const int z = blockIdx.y;
    const int i = blockIdx.x * 256 + threadIdx.x;   // float4 index
    if (z < 3) {
        const float* src = (z == 0) ? wq : (z == 1) ? wk : wv;
        float4 v = ((const float4*)src)[i];
        ((float4*)(g_wc + (size_t)z * DM * OD))[i] =
            make_float4(ftff(v.x), ftff(v.y), ftff(v.z), ftff(v.w));
    } else if (i < MR / 4) {
        float4 m = ((const float4*)vmask)[i];
        ((float4*)g_bias)[i] = make_float4(
            ((1.f - m.x) * 1e10f + 12.f) * LOG2E, ((1.f - m.y) * 1e10f + 12.f) * LOG2E,
            ((1.f - m.z) * 1e10f + 12.f) * LOG2E, ((1.f - m.w) * 1e10f + 12.f) * LOG2E);
    }
}

// ===========================================================================
// Projection GEMM (R8 proven): C = A x W, CTA 128x128, K-chunk 32, 8 warps.
// ===========================================================================
#define PA_STR 36
#define PB_STR 136
#define SA_SZ (128*PA_STR)          // 4608 words
#define SB_SZ (32*PB_STR)           // 4352 words
#define PS_WORDS (2*SA_SZ + 2*SB_SZ)
#define PS_BYTES (PS_WORDS*4)       // 71680 B

__global__ void __launch_bounds__(256, 2) proj_tc(
    const float* __restrict__ qin, const float* __restrict__ kin,
    const float* __restrict__ vin)
{
    extern __shared__ unsigned smp[];

    const float* A; const float* W; float* C; float osc;
    if (blockIdx.z == 0)      { A = qin; W = g_wc;           C = g_qw; osc = 0.125f * LOG2E; }
    else if (blockIdx.z == 1) { A = kin; W = g_wc + DM*OD;   C = g_kw; osc = 1.0f; }
    else                      { A = vin; W = g_wc + 2*DM*OD; C = g_vw; osc = 1.0f; }

    const int tid  = threadIdx.x;
    const int lane = tid & 31;
    const int wid  = tid >> 5;
    const int g = lane >> 2, t = lane & 3;
    const int wm = wid & 3, wn = wid >> 2;
    const int row0 = blockIdx.y * 128;
    const int col0 = blockIdx.x * 128;
    const unsigned sb = smem_u32(smp);

    // staging maps
    const int aArow[4] = { (tid+0)>>3, (tid+256)>>3, (tid+512)>>3, (tid+768)>>3 };
    const int aAc4 = (tid & 7) * 4;
    const int aBkk[4] = { (tid+0)>>5, (tid+256)>>5, (tid+512)>>5, (tid+768)>>5 };
    const int aBn4 = (tid & 31) * 4;

    // ldmatrix lane addresses for A fragments (buffer-0 base)
    const int mrow = lane & 15;
    const int mcol = (lane >> 4) * 4;
    unsigned aaddr[2];
    #pragma unroll
    for (int i = 0; i < 2; i++)
        aaddr[i] = sb + (unsigned)((wm*32 + 16*i + mrow)*PA_STR + mcol)*4;

    float acc[2][8][4];
    #pragma unroll
    for (int i = 0; i < 2; i++)
        #pragma unroll
        for (int j = 0; j < 8; j++)
            #pragma unroll
            for (int r = 0; r < 4; r++) acc[i][j][r] = 0.f;

    // prologue: A chunk0 -> regs; W chunk0 -> sB0 via cp.async
    float4 areg[4];
    #pragma unroll
    for (int u = 0; u < 4; u++) {
        areg[u] = *(const float4*)(A + (size_t)(row0 + aArow[u]) * DM + aAc4);
        cpa16(sb + (unsigned)(2*SA_SZ + aBkk[u]*PB_STR + aBn4) * 4,
              W + (size_t)aBkk[u] * OD + col0 + aBn4);
    }
    CP_COMMIT();

    for (int c = 0; c < DM/32; c++) {
        const int buf = c & 1;
        unsigned* sA = smp + buf * SA_SZ;
        const unsigned* sB = smp + 2*SA_SZ + buf * SB_SZ;
        const unsigned abufofs = (unsigned)(buf * SA_SZ) * 4;

        // stage A chunk c (cvt) into sA[buf]
        #pragma unroll
        for (int u = 0; u < 4; u++)
            *(uint4*)&sA[aArow[u]*PA_STR + aAc4] =
                make_uint4(ftf(areg[u].x), ftf(areg[u].y), ftf(areg[u].z), ftf(areg[u].w));
        // prefetch A chunk c+1
        if (c + 1 < DM/32) {
            #pragma unroll
            for (int u = 0; u < 4; u++)
                areg[u] = *(const float4*)(A + (size_t)(row0 + aArow[u]) * DM
                                             + (c+1)*32 + aAc4);
        }
        CP_WAIT0();
        __syncthreads();
        // issue W chunk c+1 into other buffer
        if (c + 1 < DM/32) {
            unsigned wdst = sb + (unsigned)(2*SA_SZ + (buf^1) * SB_SZ) * 4;
            #pragma unroll
            for (int u = 0; u < 4; u++)
                cpa16(wdst + (unsigned)(aBkk[u]*PB_STR + aBn4) * 4,
                      W + (size_t)((c+1)*32 + aBkk[u]) * OD + col0 + aBn4);
            CP_COMMIT();
        }

        #pragma unroll
        for (int ks = 0; ks < 4; ks++) {
            unsigned a[2][4], b[8][2];
            #pragma unroll
            for (int i = 0; i < 2; i++)
                ldsm4(a[i], aaddr[i] + abufofs + ks * 32);
            #pragma unroll
            for (int j = 0; j < 8; j++) {
                const unsigned* p = &sB[(ks*8 + t)*PB_STR + wn*64 + 8*j + g];
                b[j][0] = p[0];
                b[j][1] = p[4*PB_STR];
            }
            #pragma unroll
            for (int i = 0; i < 2; i++)
                #pragma unroll
                for (int j = 0; j < 8; j++)
                    mma8(acc[i][j], a[i], b[j]);
        }
    }

    // epilogue: scale (Q only) then tf32-round
    #pragma unroll
    for (int i = 0; i < 2; i++) {
        int row = row0 + wm*32 + 16*i + g;
        #pragma unroll
        for (int j = 0; j < 8; j++) {
            int col = col0 + wn*64 + 8*j + 2*t;
            *(float2*)(C + (size_t)row * OD + col) =
                make_float2(ftff(acc[i][j][0] * osc), ftff(acc[i][j][1] * osc));
            *(float2*)(C + (size_t)(row+8) * OD + col) =
                make_float2(ftff(acc[i][j][2] * osc), ftff(acc[i][j][3] * osc));
        }
    }
}

// ===========================================================================
// Attention R12: R11 base + half-tile phase pipelining.
// Per kt: S_A(keys 0-31) -> exp_A -> S_B(keys 32-63) -> PV_A -> exp_B -> PV_B.
// Halves the live S registers and interleaves tensor work with exp/shuffles.
// smem words: Q[128][68], K[2][64][68], V[2][64][72], bias[2][64].
// ===========================================================================
#define QST 68
#define KST 68
#define VST 72
#define QOF 0
#define KOF (128*QST)          // 8704
#define KBUF (64*KST)          // 4352
#define VOF (KOF + 2*KBUF)     // 17408
#define VBUF (64*VST)          // 4608
#define BOF (VOF + 2*VBUF)     // 26624
#define AS_WORDS (BOF + 128)   // 26752
#define AS_BYTES (AS_WORDS*4)  // 107008
#define NKT (SEQ/64)           // 32

__global__ void __launch_bounds__(128, 2) attn_tc(
    const float* __restrict__ qmask, float* __restrict__ out)
{
    extern __shared__ unsigned sm[];
    float* smF = (float*)sm;
    const int tid  = threadIdx.x;
    const int lane = tid & 31;
    const int w    = tid >> 5;
    const int g = lane >> 2, t = lane & 3;
    const int b  = blockIdx.z;
    const int h  = blockIdx.y;
    const int q0 = blockIdx.x * 128;
    const unsigned sb = smem_u32(sm);

    // staging maps (128 threads; K/V tile 64x64 -> 8 chunks, Q 128x64 -> 16)
    const int srow[8] = { (tid+0)>>4, (tid+128)>>4, (tid+256)>>4, (tid+384)>>4,
                          (tid+512)>>4, (tid+640)>>4, (tid+768)>>4, (tid+896)>>4 };
    const int sc4 = (tid & 15) * 4;

    // ---- prologue: Q + tile0 K/V/bias via cp.async (one group) ----
    {
        const float* Qg = g_qw + (size_t)(b*SEQ + q0) * OD + h*HD;
        #pragma unroll
        for (int u = 0; u < 16; u++) {
            int idx = tid + 128*u;
            int row = idx >> 4;
            cpa16(sb + (unsigned)(QOF + row*QST + sc4)*4, Qg + (size_t)row*OD + sc4);
        }
        const float* Kg = g_kw + (size_t)(b*SEQ) * OD + h*HD;
        const float* Vg = g_vw + (size_t)(b*SEQ) * OD + h*HD;
        #pragma unroll
        for (int u = 0; u < 8; u++) {
            cpa16(sb + (unsigned)(KOF + srow[u]*KST + sc4)*4, Kg + (size_t)srow[u]*OD + sc4);
            cpa16(sb + (unsigned)(VOF + srow[u]*VST + sc4)*4, Vg + (size_t)srow[u]*OD + sc4);
        }
        if (tid < 16)
            cpa16(sb + (unsigned)(BOF + tid*4)*4, g_bias + (size_t)b*SEQ + tid*4);
        CP_COMMIT();
    }

    // ---- ldmatrix lane addresses ----
    const int mrow = lane & 15;
    const int mcol = (lane >> 4) * 4;
    unsigned kaddr0[4];
    #pragma unroll
    for (int jp = 0; jp < 4; jp++)
        kaddr0[jp] = sb + (unsigned)(KOF + (jp*16 + mrow)*KST + mcol)*4;

    // ---- wait for prologue, then hoist Q fragments into registers ----
    CP_WAIT0();
    __syncthreads();
    unsigned qa[2][8][4];
    {
        unsigned qaddr0 = sb + (unsigned)(QOF + (w*32 + mrow)*QST + mcol)*4;
        unsigned qaddr1 = sb + (unsigned)(QOF + (w*32 + 16 + mrow)*QST + mcol)*4;
        #pragma unroll
        for (int ks = 0; ks < 8; ks++) {
            ldsm4(qa[0][ks], qaddr0 + ks*32);
            ldsm4(qa[1][ks], qaddr1 + ks*32);
        }
    }

    float o[2][8][4];
    #pragma unroll
    for (int i = 0; i < 2; i++)
        #pragma unroll
        for (int j = 0; j < 8; j++)
            #pragma unroll
            for (int r = 0; r < 4; r++) o[i][j][r] = 0.f;
    float l[2][2] = {{0.f, 0.f}, {0.f, 0.f}};

    const int srcl = (lane & ~3) | (t >> 1);
    const bool odd = (t & 1);

    for (int kt = 0; kt < NKT; kt++) {
        const int buf = kt & 1;
        if (kt > 0) {
            CP_WAIT0();
            __syncthreads();
        }

        // issue K/V/bias for kt+1 into the other buffer (overlaps compute)
        if (kt + 1 < NKT) {
            const int k1 = (kt + 1) * 64;
            const float* Kg = g_kw + (size_t)(b*SEQ + k1) * OD + h*HD;
            const float* Vg = g_vw + (size_t)(b*SEQ + k1) * OD + h*HD;
            unsigned kdst = sb + (unsigned)(KOF + (buf^1)*KBUF)*4;
            unsigned vdst = sb + (unsigned)(VOF + (buf^1)*VBUF)*4;
            #pragma unroll
            for (int u = 0; u < 8; u++) {
                cpa16(kdst + (unsigned)(srow[u]*KST + sc4)*4, Kg + (size_t)srow[u]*OD + sc4);
                cpa16(vdst + (unsigned)(srow[u]*VST + sc4)*4, Vg + (size_t)srow[u]*OD + sc4);
            }
            if (tid < 16)
                cpa16(sb + (unsigned)(BOF + (buf^1)*64 + tid*4)*4,
                      g_bias + (size_t)b*SEQ + k1 + tid*4);
            CP_COMMIT();
        }

        const unsigned kofs = (unsigned)(buf * KBUF) * 4;
        const int vbase = VOF + buf * VBUF;
        const int bbase = BOF + buf * 64;

        float sA[2][4][4], sB2[2][4][4];

        // ---- S_A : keys 0..31 (j=0..3, jp=0..1) ----
        #pragma unroll
        for (int i = 0; i < 2; i++)
            #pragma unroll
            for (int j = 0; j < 4; j++)
                #pragma unroll
                for (int r = 0; r < 4; r++) sA[i][j][r] = 0.f;
        #pragma unroll
        for (int ks = 0; ks < 8; ks++) {
            unsigned bb[2][4];
            ldsm4(bb[0], kaddr0[0] + kofs + ks*32);
            ldsm4(bb[1], kaddr0[1] + kofs + ks*32);
            #pragma unroll
            for (int j = 0; j < 4; j++) {
                unsigned bfr[2] = { bb[j>>1][j&1], bb[j>>1][2+(j&1)] };
                mma8(sA[0][j], qa[0][ks], bfr);
                mma8(sA[1][j], qa[1][ks], bfr);
            }
        }

        // ---- exp_A ----
        #pragma unroll
        for (int j = 0; j < 4; j++) {
            float bl = smF[bbase + 8*j + 2*t];
            float bh = smF[bbase + 8*j + 2*t + 1];
            #pragma unroll
            for (int i = 0; i < 2; i++) {
                float p0 = ex2(sA[i][j][0] - bl);
                float p1 = ex2(sA[i][j][1] - bh);
                float p2 = ex2(sA[i][j][2] - bl);
                float p3 = ex2(sA[i][j][3] - bh);
                l[i][0] += p0 + p1;
                l[i][1] += p2 + p3;
                sA[i][j][0] = p0; sA[i][j][1] = p1; sA[i][j][2] = p2; sA[i][j][3] = p3;
            }
        }

        // ---- S_B : keys 32..63 (j=4..7, jp=2..3) ----
        #pragma unroll
        for (int i = 0; i < 2; i++)
            #pragma unroll
            for (int j = 0; j < 4; j++)
                #pragma unroll
                for (int r = 0; r < 4; r++) sB2[i][j][r] = 0.f;
        #pragma unroll
        for (int ks = 0; ks < 8; ks++) {
            unsigned bb[2][4];
            ldsm4(bb[0], kaddr0[2] + kofs + ks*32);
            ldsm4(bb[1], kaddr0[3] + kofs + ks*32);
            #pragma unroll
            for (int j = 0; j < 4; j++) {
                unsigned bfr[2] = { bb[j>>1][j&1], bb[j>>1][2+(j&1)] };
                mma8(sB2[0][j], qa[0][ks], bfr);
                mma8(sB2[1][j], qa[1][ks], bfr);
            }
        }

        // ---- PV_A : key rows 0..31 (ksv=0..3), P from sA ----
        #pragma unroll
        for (int ksv = 0; ksv < 4; ksv++) {
            unsigned a[2][4];
            #pragma unroll
            for (int i = 0; i < 2; i++) {
                float v00 = __shfl_sync(0xffffffffu, sA[i][ksv][0], srcl);
                float v01 = __shfl_sync(0xffffffffu, sA[i][ksv][1], srcl);
                float v10 = __shfl_sync(0xffffffffu, sA[i][ksv][2], srcl);
                float v11 = __shfl_sync(0xffffffffu, sA[i][ksv][3], srcl);
                float v20 = __shfl_sync(0xffffffffu, sA[i][ksv][0], srcl + 2);
                float v21 = __shfl_sync(0xffffffffu, sA[i][ksv][1], srcl + 2);
                float v30 = __shfl_sync(0xffffffffu, sA[i][ksv][2], srcl + 2);
                float v31 = __shfl_sync(0xffffffffu, sA[i][ksv][3], srcl + 2);
                a[i][0] = ftf(odd ? v01 : v00);
                a[i][1] = ftf(odd ? v11 : v10);
                a[i][2] = ftf(odd ? v21 : v20);
                a[i][3] = ftf(odd ? v31 : v30);
            }
            #pragma unroll
            for (int j = 0; j < 8; j++) {
                unsigned bfr[2];
                bfr[0] = sm[vbase + (ksv*8 + t)*VST + 8*j + g];
                bfr[1] = sm[vbase + (ksv*8 + t + 4)*VST + 8*j + g];
                mma8(o[0][j], a[0], bfr);
                mma8(o[1][j], a[1], bfr);
            }
        }

        // ---- exp_B ----
        #pragma unroll
        for (int j = 0; j < 4; j++) {
            float bl = smF[bbase + 32 + 8*j + 2*t];
            float bh = smF[bbase + 32 + 8*j + 2*t + 1];
            #pragma unroll
            for (int i = 0; i < 2; i++) {
                float p0 = ex2(sB2[i][j][0] - bl);
                float p1 = ex2(sB2[i][j][1] - bh);
                float p2 = ex2(sB2[i][j][2] - bl);
                float p3 = ex2(sB2[i][j][3] - bh);
                l[i][0] += p0 + p1;
                l[i][1] += p2 + p3;
                sB2[i][j][0] = p0; sB2[i][j][1] = p1; sB2[i][j][2] = p2; sB2[i][j][3] = p3;
            }
        }

        // ---- PV_B : key rows 32..63 (ksv=4..7), P from sB2 ----
        #pragma unroll
        for (int ksv = 4; ksv < 8; ksv++) {
            unsigned a[2][4];
            #pragma unroll
            for (int i = 0; i < 2; i++) {
                float v00 = __shfl_sync(0xffffffffu, sB2[i][ksv-4][0], srcl);
                float v01 = __shfl_sync(0xffffffffu, sB2[i][ksv-4][1], srcl);
                float v10 = __shfl_sync(0xffffffffu, sB2[i][ksv-4][2], srcl);
                float v11 = __shfl_sync(0xffffffffu, sB2[i][ksv-4][3], srcl);
                float v20 = __shfl_sync(0xffffffffu, sB2[i][ksv-4][0], srcl + 2);
                float v21 = __shfl_sync(0xffffffffu, sB2[i][ksv-4][1], srcl + 2);
                float v30 = __shfl_sync(0xffffffffu, sB2[i][ksv-4][2], srcl + 2);
                float v31 = __shfl_sync(0xffffffffu, sB2[i][ksv-4][3], srcl + 2);
                a[i][0] = ftf(odd ? v01 : v00);
                a[i][1] = ftf(odd ? v11 : v10);
                a[i][2] = ftf(odd ? v21 : v20);
                a[i][3] = ftf(odd ? v31 : v30);
            }
            #pragma unroll
            for (int j = 0; j < 8; j++) {
                unsigned bfr[2];
                bfr[0] = sm[vbase + (ksv*8 + t)*VST + 8*j + g];
                bfr[1] = sm[vbase + (ksv*8 + t + 4)*VST + 8*j + g];
                mma8(o[0][j], a[0], bfr);
                mma8(o[1][j], a[1], bfr);
            }
        }
    }

    // ---- epilogue: reduce l over quad lanes, normalize, q_mask, store ----
    #pragma unroll
    for (int i = 0; i < 2; i++) {
        l[i][0] += __shfl_xor_sync(0xffffffffu, l[i][0], 1);
        l[i][0] += __shfl_xor_sync(0xffffffffu, l[i][0], 2);
        l[i][1] += __shfl_xor_sync(0xffffffffu, l[i][1], 1);
        l[i][1] += __shfl_xor_sync(0xffffffffu, l[i][1], 2);
    }
    float* O = out + (size_t)(b*SEQ + q0) * OD + h*HD;
    #pragma unroll
    for (int i = 0; i < 2; i++) {
        int r0 = w*32 + 16*i + g;
        float f0 = qmask[(size_t)b*SEQ + q0 + r0] / l[i][0];
        float f1 = qmask[(size_t)b*SEQ + q0 + r0 + 8] / l[i][1];
        #pragma unroll
        for (int j = 0; j < 8; j++) {
            int col = 8*j + 2*t;
            *(float2*)(O + (size_t)r0 * OD + col) =
                make_float2(o[i][j][0] * f0, o[i][j][1] * f0);
            *(float2*)(O + (size_t)(r0+8) * OD + col) =
                make_float2(o[i][j][2] * f1, o[i][j][3] * f1);
        }
    }
}

// ===========================================================================
extern "C" void kernel_launch(void* const* d_in, const int* in_sizes, int n_in,
                              void* d_out, int out_size)
{
    const float* q     = (const float*)d_in[0];
    const float* k     = (const float*)d_in[1];
    const float* v     = (const float*)d_in[2];
    const float* vmask = (const float*)d_in[3];
    const float* qmask = (const float*)d_in[4];
    const float* wq    = (const float*)d_in[5];
    const float* wk    = (const float*)d_in[6];
    const float* wv    = (const float*)d_in[7];
    float* out = (float*)d_out;

    cudaFuncSetAttribute(proj_tc, cudaFuncAttributeMaxDynamicSharedMemorySize, PS_BYTES);
    cudaFuncSetAttribute(attn_tc, cudaFuncAttributeMaxDynamicSharedMemorySize, AS_BYTES);

    dim3 gg(1024, 4);
    prepass<<<gg, 256>>>(wq, wk, wv, vmask);

    dim3 pg(OD / 128, MR / 128, 3);       // 8 x 32 x 3
    proj_tc<<<pg, 256, PS_BYTES>>>(q, k, v);

    dim3 ag(SEQ / 128, NH, BATCH);        // 16 x 16 x 2
    attn_tc<<<ag, 128, AS_BYTES>>>(qmask, out);
}

// round 13
// speedup vs baseline: 1.0443x; 1.0443x over previous
#include <cuda_runtime.h>
#include <math.h>

#define BATCH 2
#define SEQ 2048
#define DM 1024
#define OD 1024
#define NH 16
#define HD 64
#define MR (BATCH*SEQ)   // 4096
#define LOG2E 1.4426950408889634f

// Projection outputs (tf32-rounded fp32; Q pre-scaled by log2e/8): [B*SEQ][OD]
__device__ float g_qw[MR*OD];
__device__ float g_kw[MR*OD];
__device__ float g_vw[MR*OD];
// Pre-converted weights, TRANSPOSED (tf32-rounded): 3 x [OD][DM]
__device__ float g_wc[3*DM*OD];
// softmax bias (log2 domain)
__device__ float g_bias[MR];

// ---------------------------------------------------------------------------
// helpers
// ---------------------------------------------------------------------------
__device__ __forceinline__ unsigned ftf(float x) {
    unsigned r; asm("cvt.rna.tf32.f32 %0, %1;" : "=r"(r) : "f"(x)); return r;
}
__device__ __forceinline__ float ftff(float x) {
    return __uint_as_float(ftf(x));
}
__device__ __forceinline__ float ex2(float x) {
    float r; asm("ex2.approx.f32 %0, %1;" : "=f"(r) : "f"(x)); return r;
}
__device__ __forceinline__ unsigned smem_u32(const void* p) {
    unsigned a;
    asm("{ .reg .u64 t; cvta.to.shared.u64 t, %1; cvt.u32.u64 %0, t; }"
        : "=r"(a) : "l"(p));
    return a;
}
__device__ __forceinline__ void cpa16(unsigned dst, const void* src) {
    asm volatile("cp.async.cg.shared.global [%0], [%1], 16;"
                 :: "r"(dst), "l"(src) : "memory");
}
#define CP_COMMIT() asm volatile("cp.async.commit_group;" ::: "memory")
#define CP_WAIT0()  asm volatile("cp.async.wait_group 0;" ::: "memory")

// D += A(16x8,row) * B(8x8,col)  tf32, fp32 accum
__device__ __forceinline__ void mma8(float* d, const unsigned* a, const unsigned* b) {
    asm volatile(
        "mma.sync.aligned.m16n8k8.row.col.f32.tf32.tf32.f32 "
        "{%0,%1,%2,%3}, {%4,%5,%6,%7}, {%8,%9}, {%0,%1,%2,%3};"
        : "+f"(d[0]), "+f"(d[1]), "+f"(d[2]), "+f"(d[3])
        : "r"(a[0]), "r"(a[1]), "r"(a[2]), "r"(a[3]), "r"(b[0]), "r"(b[1]));
}
// ldmatrix x4 on 32-bit words
__device__ __forceinline__ void ldsm4(unsigned* r, unsigned addr) {
    asm volatile("ldmatrix.sync.aligned.m8n8.x4.shared.b16 {%0,%1,%2,%3}, [%4];"
        : "=r"(r[0]), "=r"(r[1]), "=r"(r[2]), "=r"(r[3]) : "r"(addr));
}

// ===========================================================================
// Prepass: transpose + tf32-round weights (g_wc = W^T, [OD][DM]);
// precompute log2-domain softmax bias. grid (32,32,4), block (32,8).
// ===========================================================================
__global__ __launch_bounds__(256) void prepass(
    const float* __restrict__ wq, const float* __restrict__ wk,
    const float* __restrict__ wv, const float* __restrict__ vmask)
{
    const int z = blockIdx.z;
    if (z < 3) {
        __shared__ float tile[32][33];
        const float* src = (z == 0) ? wq : (z == 1) ? wk : wv;
        float* dst = g_wc + (size_t)z * DM * OD;
        int x = blockIdx.x * 32 + threadIdx.x;   // n
        int y = blockIdx.y * 32 + threadIdx.y;   // k
        #pragma unroll
        for (int j = 0; j < 32; j += 8)
            tile[threadIdx.y + j][threadIdx.x] = src[(size_t)(y + j) * OD + x];
        __syncthreads();
        int x2 = blockIdx.y * 32 + threadIdx.x;  // k
        int y2 = blockIdx.x * 32 + threadIdx.y;  // n
        #pragma unroll
        for (int j = 0; j < 32; j += 8)
            dst[(size_t)(y2 + j) * DM + x2] = ftff(tile[threadIdx.x][threadIdx.y + j]);
    } else if (blockIdx.y == 0) {
        int i = blockIdx.x * 256 + threadIdx.y * 32 + threadIdx.x;  // float4 idx
        if (i < MR / 4) {
            float4 m = ((const float4*)vmask)[i];
            ((float4*)g_bias)[i] = make_float4(
                ((1.f - m.x) * 1e10f + 12.f) * LOG2E, ((1.f - m.y) * 1e10f + 12.f) * LOG2E,
                ((1.f - m.z) * 1e10f + 12.f) * LOG2E, ((1.f - m.w) * 1e10f + 12.f) * LOG2E);
        }
    }
}

// ===========================================================================
// Projection GEMM: C = A x W, CTA 128x128, K-chunk 32, 8 warps (4m x 2n).
// W^T (pre-transposed, pre-rounded) via cp.async -> B frags via ldmatrix,
// exactly like attn's K path. A via register prefetch + cvt + ldmatrix.
// Q scaled by log2e/8 before tf32 rounding.
// ===========================================================================
#define PA_STR 36
#define PB_STR 36
#define SA_SZ (128*PA_STR)          // 4608 words
#define SB_SZ (128*PB_STR)          // 4608 words
#define PS_WORDS (2*SA_SZ + 2*SB_SZ)
#define PS_BYTES (PS_WORDS*4)       // 73728 B

__global__ void __launch_bounds__(256, 2) proj_tc(
    const float* __restrict__ qin, const float* __restrict__ kin,
    const float* __restrict__ vin)
{
    extern __shared__ unsigned smp[];

    const float* A; const float* Wt; float* C; float osc;
    if (blockIdx.z == 0)      { A = qin; Wt = g_wc;           C = g_qw; osc = 0.125f * LOG2E; }
    else if (blockIdx.z == 1) { A = kin; Wt = g_wc + DM*OD;   C = g_kw; osc = 1.0f; }
    else                      { A = vin; Wt = g_wc + 2*DM*OD; C = g_vw; osc = 1.0f; }

    const int tid  = threadIdx.x;
    const int lane = tid & 31;
    const int wid  = tid >> 5;
    const int g = lane >> 2, t = lane & 3;
    const int wm = wid & 3, wn = wid >> 2;
    const int row0 = blockIdx.y * 128;
    const int col0 = blockIdx.x * 128;
    const unsigned sb = smem_u32(smp);

    // staging maps (shared by A and W^T tiles: [128 rows][32 k])
    const int aArow[4] = { (tid+0)>>3, (tid+256)>>3, (tid+512)>>3, (tid+768)>>3 };
    const int aAc4 = (tid & 7) * 4;

    // ldmatrix lane addresses (buffer-0 bases)
    const int mrow = lane & 15;
    const int mcol = (lane >> 4) * 4;
    unsigned aaddr[2], baddr[4];
    #pragma unroll
    for (int i = 0; i < 2; i++)
        aaddr[i] = sb + (unsigned)((wm*32 + 16*i + mrow)*PA_STR + mcol)*4;
    #pragma unroll
    for (int jp = 0; jp < 4; jp++)
        baddr[jp] = sb + (unsigned)(2*SA_SZ + (wn*64 + jp*16 + mrow)*PB_STR + mcol)*4;

    float acc[2][8][4];
    #pragma unroll
    for (int i = 0; i < 2; i++)
        #pragma unroll
        for (int j = 0; j < 8; j++)
            #pragma unroll
            for (int r = 0; r < 4; r++) acc[i][j][r] = 0.f;

    // prologue: A chunk0 -> regs; W^T chunk0 -> sB0 via cp.async
    float4 areg[4];
    #pragma unroll
    for (int u = 0; u < 4; u++) {
        areg[u] = *(const float4*)(A + (size_t)(row0 + aArow[u]) * DM + aAc4);
        cpa16(sb + (unsigned)(2*SA_SZ + aArow[u]*PB_STR + aAc4) * 4,
              Wt + (size_t)(col0 + aArow[u]) * DM + aAc4);
    }
    CP_COMMIT();

    for (int c = 0; c < DM/32; c++) {
        const int buf = c & 1;
        unsigned* sA = smp + buf * SA_SZ;
        const unsigned abufofs = (unsigned)(buf * SA_SZ) * 4;
        const unsigned bbufofs = (unsigned)(buf * SB_SZ) * 4;

        // stage A chunk c (cvt) into sA[buf]
        #pragma unroll
        for (int u = 0; u < 4; u++)
            *(uint4*)&sA[aArow[u]*PA_STR + aAc4] =
                make_uint4(ftf(areg[u].x), ftf(areg[u].y), ftf(areg[u].z), ftf(areg[u].w));
        // prefetch A chunk c+1
        if (c + 1 < DM/32) {
            #pragma unroll
            for (int u = 0; u < 4; u++)
                areg[u] = *(const float4*)(A + (size_t)(row0 + aArow[u]) * DM
                                             + (c+1)*32 + aAc4);
        }
        CP_WAIT0();
        __syncthreads();
        // issue W^T chunk c+1 into other buffer
        if (c + 1 < DM/32) {
            unsigned wdst = sb + (unsigned)(2*SA_SZ + (buf^1) * SB_SZ) * 4;
            #pragma unroll
            for (int u = 0; u < 4; u++)
                cpa16(wdst + (unsigned)(aArow[u]*PB_STR + aAc4) * 4,
                      Wt + (size_t)(col0 + aArow[u]) * DM + (c+1)*32 + aAc4);
            CP_COMMIT();
        }

        #pragma unroll
        for (int ks = 0; ks < 4; ks++) {
            unsigned a[2][4], bb[4][4];
            #pragma unroll
            for (int i = 0; i < 2; i++)
                ldsm4(a[i], aaddr[i] + abufofs + ks * 32);
            #pragma unroll
            for (int jp = 0; jp < 4; jp++)
                ldsm4(bb[jp], baddr[jp] + bbufofs + ks * 32);
            #pragma unroll
            for (int j = 0; j < 8; j++) {
                unsigned bfr[2] = { bb[j>>1][j&1], bb[j>>1][2+(j&1)] };
                mma8(acc[0][j], a[0], bfr);
                mma8(acc[1][j], a[1], bfr);
            }
        }
    }

    // epilogue: scale (Q only) then tf32-round
    #pragma unroll
    for (int i = 0; i < 2; i++) {
        int row = row0 + wm*32 + 16*i + g;
        #pragma unroll
        for (int j = 0; j < 8; j++) {
            int col = col0 + wn*64 + 8*j + 2*t;
            *(float2*)(C + (size_t)row * OD + col) =
                make_float2(ftff(acc[i][j][0] * osc), ftff(acc[i][j][1] * osc));
            *(float2*)(C + (size_t)(row+8) * OD + col) =
                make_float2(ftff(acc[i][j][2] * osc), ftff(acc[i][j][3] * osc));
        }
    }
}

// ===========================================================================
// Attention (R11 frozen): CTA = (b, h, 128 q rows), 4 warps, 32q x 64k tile.
// K/V/bias via cp.async double-buffered pipeline; Q frags hoisted to regs.
// log2-domain softmax, bare ex2. Shuffle-based P conversion.
// smem words: Q[128][68], K[2][64][68], V[2][64][72], bias[2][64].
// ===========================================================================
#define QST 68
#define KST 68
#define VST 72
#define QOF 0
#define KOF (128*QST)          // 8704
#define KBUF (64*KST)          // 4352
#define VOF (KOF + 2*KBUF)     // 17408
#define VBUF (64*VST)          // 4608
#define BOF (VOF + 2*VBUF)     // 26624
#define AS_WORDS (BOF + 128)   // 26752
#define AS_BYTES (AS_WORDS*4)  // 107008
#define NKT (SEQ/64)           // 32

__global__ void __launch_bounds__(128, 2) attn_tc(
    const float* __restrict__ qmask, float* __restrict__ out)
{
    extern __shared__ unsigned sm[];
    float* smF = (float*)sm;
    const int tid  = threadIdx.x;
    const int lane = tid & 31;
    const int w    = tid >> 5;
    const int g = lane >> 2, t = lane & 3;
    const int b  = blockIdx.z;
    const int h  = blockIdx.y;
    const int q0 = blockIdx.x * 128;
    const unsigned sb = smem_u32(sm);

    // staging maps (128 threads; K/V tile 64x64 -> 8 chunks, Q 128x64 -> 16)
    const int srow[8] = { (tid+0)>>4, (tid+128)>>4, (tid+256)>>4, (tid+384)>>4,
                          (tid+512)>>4, (tid+640)>>4, (tid+768)>>4, (tid+896)>>4 };
    const int sc4 = (tid & 15) * 4;

    // ---- prologue: Q + tile0 K/V/bias via cp.async (one group) ----
    {
        const float* Qg = g_qw + (size_t)(b*SEQ + q0) * OD + h*HD;
        #pragma unroll
        for (int u = 0; u < 16; u++) {
            int idx = tid + 128*u;
            int row = idx >> 4;
            cpa16(sb + (unsigned)(QOF + row*QST + sc4)*4, Qg + (size_t)row*OD + sc4);
        }
        const float* Kg = g_kw + (size_t)(b*SEQ) * OD + h*HD;
        const float* Vg = g_vw + (size_t)(b*SEQ) * OD + h*HD;
        #pragma unroll
        for (int u = 0; u < 8; u++) {
            cpa16(sb + (unsigned)(KOF + srow[u]*KST + sc4)*4, Kg + (size_t)srow[u]*OD + sc4);
            cpa16(sb + (unsigned)(VOF + srow[u]*VST + sc4)*4, Vg + (size_t)srow[u]*OD + sc4);
        }
        if (tid < 16)
            cpa16(sb + (unsigned)(BOF + tid*4)*4, g_bias + (size_t)b*SEQ + tid*4);
        CP_COMMIT();
    }

    // ---- ldmatrix lane addresses ----
    const int mrow = lane & 15;
    const int mcol = (lane >> 4) * 4;
    unsigned kaddr0[4];
    #pragma unroll
    for (int jp = 0; jp < 4; jp++)
        kaddr0[jp] = sb + (unsigned)(KOF + (jp*16 + mrow)*KST + mcol)*4;

    // ---- wait for prologue, then hoist Q fragments into registers ----
    CP_WAIT0();
    __syncthreads();
    unsigned qa[2][8][4];
    {
        unsigned qaddr0 = sb + (unsigned)(QOF + (w*32 + mrow)*QST + mcol)*4;
        unsigned qaddr1 = sb + (unsigned)(QOF + (w*32 + 16 + mrow)*QST + mcol)*4;
        #pragma unroll
        for (int ks = 0; ks < 8; ks++) {
            ldsm4(qa[0][ks], qaddr0 + ks*32);
            ldsm4(qa[1][ks], qaddr1 + ks*32);
        }
    }

    float o[2][8][4];
    #pragma unroll
    for (int i = 0; i < 2; i++)
        #pragma unroll
        for (int j = 0; j < 8; j++)
            #pragma unroll
            for (int r = 0; r < 4; r++) o[i][j][r] = 0.f;
    float l[2][2] = {{0.f, 0.f}, {0.f, 0.f}};

    for (int kt = 0; kt < NKT; kt++) {
        const int buf = kt & 1;
        if (kt > 0) {
            CP_WAIT0();
            __syncthreads();
        }

        // issue K/V/bias for kt+1 into the other buffer (overlaps compute)
        if (kt + 1 < NKT) {
            const int k1 = (kt + 1) * 64;
            const float* Kg = g_kw + (size_t)(b*SEQ + k1) * OD + h*HD;
            const float* Vg = g_vw + (size_t)(b*SEQ + k1) * OD + h*HD;
            unsigned kdst = sb + (unsigned)(KOF + (buf^1)*KBUF)*4;
            unsigned vdst = sb + (unsigned)(VOF + (buf^1)*VBUF)*4;
            #pragma unroll
            for (int u = 0; u < 8; u++) {
                cpa16(kdst + (unsigned)(srow[u]*KST + sc4)*4, Kg + (size_t)srow[u]*OD + sc4);
                cpa16(vdst + (unsigned)(srow[u]*VST + sc4)*4, Vg + (size_t)srow[u]*OD + sc4);
            }
            if (tid < 16)
                cpa16(sb + (unsigned)(BOF + (buf^1)*64 + tid*4)*4,
                      g_bias + (size_t)b*SEQ + k1 + tid*4);
            CP_COMMIT();
        }

        const unsigned kofs = (unsigned)(buf * KBUF) * 4;
        const int vbase = VOF + buf * VBUF;
        const int bbase = BOF + buf * 64;

        // ---- S' = (Q*log2e/8) K^T : warp tile 32 x 64, Q from registers ----
        float s[2][8][4];
        #pragma unroll
        for (int i = 0; i < 2; i++)
            #pragma unroll
            for (int j = 0; j < 8; j++)
                #pragma unroll
                for (int r = 0; r < 4; r++) s[i][j][r] = 0.f;

        #pragma unroll
        for (int ks = 0; ks < 8; ks++) {
            unsigned bb[4][4];
            #pragma unroll
            for (int jp = 0; jp < 4; jp++) ldsm4(bb[jp], kaddr0[jp] + kofs + ks*32);
            #pragma unroll
            for (int j = 0; j < 8; j++) {
                unsigned bfr[2] = { bb[j>>1][j&1], bb[j>>1][2+(j&1)] };
                mma8(s[0][j], qa[0][ks], bfr);
                mma8(s[1][j], qa[1][ks], bfr);
            }
        }

        // ---- p = 2^(s' - bias'), accumulate row sums ----
        #pragma unroll
        for (int j = 0; j < 8; j++) {
            float bl = smF[bbase + 8*j + 2*t];
            float bh = smF[bbase + 8*j + 2*t + 1];
            #pragma unroll
            for (int i = 0; i < 2; i++) {
                float p0 = ex2(s[i][j][0] - bl);
                float p1 = ex2(s[i][j][1] - bh);
                float p2 = ex2(s[i][j][2] - bl);
                float p3 = ex2(s[i][j][3] - bh);
                l[i][0] += p0 + p1;
                l[i][1] += p2 + p3;
                s[i][j][0] = p0; s[i][j][1] = p1; s[i][j][2] = p2; s[i][j][3] = p3;
            }
        }

        // ---- O += P V : P A-frags via intra-quad shuffles ----
        const int srcl = (lane & ~3) | (t >> 1);
        const bool odd = (t & 1);
        #pragma unroll
        for (int ks = 0; ks < 8; ks++) {
            unsigned a[2][4];
            #pragma unroll
            for (int i = 0; i < 2; i++) {
                float v00 = __shfl_sync(0xffffffffu, s[i][ks][0], srcl);
                float v01 = __shfl_sync(0xffffffffu, s[i][ks][1], srcl);
                float v10 = __shfl_sync(0xffffffffu, s[i][ks][2], srcl);
                float v11 = __shfl_sync(0xffffffffu, s[i][ks][3], srcl);
                float v20 = __shfl_sync(0xffffffffu, s[i][ks][0], srcl + 2);
                float v21 = __shfl_sync(0xffffffffu, s[i][ks][1], srcl + 2);
                float v30 = __shfl_sync(0xffffffffu, s[i][ks][2], srcl + 2);
                float v31 = __shfl_sync(0xffffffffu, s[i][ks][3], srcl + 2);
                a[i][0] = ftf(odd ? v01 : v00);
                a[i][1] = ftf(odd ? v11 : v10);
                a[i][2] = ftf(odd ? v21 : v20);
                a[i][3] = ftf(odd ? v31 : v30);
            }
            #pragma unroll
            for (int j = 0; j < 8; j++) {
                unsigned bfr[2];
                bfr[0] = sm[vbase + (ks*8 + t)*VST + 8*j + g];
                bfr[1] = sm[vbase + (ks*8 + t + 4)*VST + 8*j + g];
                mma8(o[0][j], a[0], bfr);
                mma8(o[1][j], a[1], bfr);
            }
        }
    }

    // ---- epilogue: reduce l over quad lanes, normalize, q_mask, store ----
    #pragma unroll
    for (int i = 0; i < 2; i++) {
        l[i][0] += __shfl_xor_sync(0xffffffffu, l[i][0], 1);
        l[i][0] += __shfl_xor_sync(0xffffffffu, l[i][0], 2);
        l[i][1] += __shfl_xor_sync(0xffffffffu, l[i][1], 1);
        l[i][1] += __shfl_xor_sync(0xffffffffu, l[i][1], 2);
    }
    float* O = out + (size_t)(b*SEQ + q0) * OD + h*HD;
    #pragma unroll
    for (int i = 0; i < 2; i++) {
        int r0 = w*32 + 16*i + g;
        float f0 = qmask[(size_t)b*SEQ + q0 + r0] / l[i][0];
        float f1 = qmask[(size_t)b*SEQ + q0 + r0 + 8] / l[i][1];
        #pragma unroll
        for (int j = 0; j < 8; j++) {
            int col = 8*j + 2*t;
            *(float2*)(O + (size_t)r0 * OD + col) =
                make_float2(o[i][j][0] * f0, o[i][j][1] * f0);
            *(float2*)(O + (size_t)(r0+8) * OD + col) =
                make_float2(o[i][j][2] * f1, o[i][j][3] * f1);
        }
    }
}

// ===========================================================================
extern "C" void kernel_launch(void* const* d_in, const int* in_sizes, int n_in,
                              void* d_out, int out_size)
{
    const float* q     = (const float*)d_in[0];
    const float* k     = (const float*)d_in[1];
    const float* v     = (const float*)d_in[2];
    const float* vmask = (const float*)d_in[3];
    const float* qmask = (const float*)d_in[4];
    const float* wq    = (const float*)d_in[5];
    const float* wk    = (const float*)d_in[6];
    const float* wv    = (const float*)d_in[7];
    float* out = (float*)d_out;

    cudaFuncSetAttribute(proj_tc, cudaFuncAttributeMaxDynamicSharedMemorySize, PS_BYTES);
    cudaFuncSetAttribute(attn_tc, cudaFuncAttributeMaxDynamicSharedMemorySize, AS_BYTES);

    dim3 gg(32, 32, 4);
    prepass<<<gg, dim3(32, 8)>>>(wq, wk, wv, vmask);

    dim3 pg(OD / 128, MR / 128, 3);       // 8 x 32 x 3
    proj_tc<<<pg, 256, PS_BYTES>>>(q, k, v);

    dim3 ag(SEQ / 128, NH, BATCH);        // 16 x 16 x 2
    attn_tc<<<ag, 128, AS_BYTES>>>(qmask, out);
}

// round 14
// speedup vs baseline: 1.1120x; 1.0649x over previous
#include <cuda_runtime.h>
#include <math.h>

#define BATCH 2
#define SEQ 2048
#define DM 1024
#define OD 1024
#define NH 16
#define HD 64
#define MR (BATCH*SEQ)   // 4096
#define LOG2E 1.4426950408889634f

// Projection outputs (tf32-rounded fp32; Q pre-scaled by log2e/8): [B*SEQ][OD]
__device__ float g_qw[MR*OD];
__device__ float g_kw[MR*OD];
__device__ float g_vw[MR*OD];
// Pre-converted weights (tf32-rounded) and softmax bias (log2 domain)
__device__ float g_wc[3*DM*OD];
__device__ float g_bias[MR];

// ---------------------------------------------------------------------------
// helpers
// ---------------------------------------------------------------------------
__device__ __forceinline__ unsigned ftf(float x) {
    unsigned r; asm("cvt.rna.tf32.f32 %0, %1;" : "=r"(r) : "f"(x)); return r;
}
__device__ __forceinline__ float ftff(float x) {
    return __uint_as_float(ftf(x));
}
__device__ __forceinline__ float ex2(float x) {
    float r; asm("ex2.approx.f32 %0, %1;" : "=f"(r) : "f"(x)); return r;
}
__device__ __forceinline__ unsigned smem_u32(const void* p) {
    unsigned a;
    asm("{ .reg .u64 t; cvta.to.shared.u64 t, %1; cvt.u32.u64 %0, t; }"
        : "=r"(a) : "l"(p));
    return a;
}
__device__ __forceinline__ void cpa16(unsigned dst, const void* src) {
    asm volatile("cp.async.cg.shared.global [%0], [%1], 16;"
                 :: "r"(dst), "l"(src) : "memory");
}
#define CP_COMMIT() asm volatile("cp.async.commit_group;" ::: "memory")
#define CP_WAIT0()  asm volatile("cp.async.wait_group 0;" ::: "memory")

// D += A(16x8,row) * B(8x8,col)  tf32, fp32 accum
__device__ __forceinline__ void mma8(float* d, const unsigned* a, const unsigned* b) {
    asm volatile(
        "mma.sync.aligned.m16n8k8.row.col.f32.tf32.tf32.f32 "
        "{%0,%1,%2,%3}, {%4,%5,%6,%7}, {%8,%9}, {%0,%1,%2,%3};"
        : "+f"(d[0]), "+f"(d[1]), "+f"(d[2]), "+f"(d[3])
        : "r"(a[0]), "r"(a[1]), "r"(a[2]), "r"(a[3]), "r"(b[0]), "r"(b[1]));
}
// ldmatrix x4 on 32-bit words
__device__ __forceinline__ void ldsm4(unsigned* r, unsigned addr) {
    asm volatile("ldmatrix.sync.aligned.m8n8.x4.shared.b16 {%0,%1,%2,%3}, [%4];"
        : "=r"(r[0]), "=r"(r[1]), "=r"(r[2]), "=r"(r[3]) : "r"(addr));
}

// ===========================================================================
// Prepass: round weights to tf32; precompute log2-domain softmax bias.
// ===========================================================================
__global__ __launch_bounds__(256) void prepass(
    const float* __restrict__ wq, const float* __restrict__ wk,
    const float* __restrict__ wv, const float* __restrict__ vmask)
{
    const int z = blockIdx.y;
    const int i = blockIdx.x * 256 + threadIdx.x;   // float4 index
    if (z < 3) {
        const float* src = (z == 0) ? wq : (z == 1) ? wk : wv;
        float4 v = ((const float4*)src)[i];
        ((float4*)(g_wc + (size_t)z * DM * OD))[i] =
            make_float4(ftff(v.x), ftff(v.y), ftff(v.z), ftff(v.w));
    } else if (i < MR / 4) {
        float4 m = ((const float4*)vmask)[i];
        ((float4*)g_bias)[i] = make_float4(
            ((1.f - m.x) * 1e10f + 12.f) * LOG2E, ((1.f - m.y) * 1e10f + 12.f) * LOG2E,
            ((1.f - m.z) * 1e10f + 12.f) * LOG2E, ((1.f - m.w) * 1e10f + 12.f) * LOG2E);
    }
}

// ===========================================================================
// Projection GEMM (R11 proven): C = A x W, CTA 128x128, K-chunk 32, 8 warps.
// rowbase selects the batch half (grid.y covers 16 row-blocks).
// ===========================================================================
#define PA_STR 36
#define PB_STR 136
#define SA_SZ (128*PA_STR)          // 4608 words
#define SB_SZ (32*PB_STR)           // 4352 words
#define PS_WORDS (2*SA_SZ + 2*SB_SZ)
#define PS_BYTES (PS_WORDS*4)       // 71680 B

__global__ void __launch_bounds__(256, 2) proj_tc(
    const float* __restrict__ qin, const float* __restrict__ kin,
    const float* __restrict__ vin, int rowbase)
{
    extern __shared__ unsigned smp[];

    const float* A; const float* W; float* C; float osc;
    if (blockIdx.z == 0)      { A = qin; W = g_wc;           C = g_qw; osc = 0.125f * LOG2E; }
    else if (blockIdx.z == 1) { A = kin; W = g_wc + DM*OD;   C = g_kw; osc = 1.0f; }
    else                      { A = vin; W = g_wc + 2*DM*OD; C = g_vw; osc = 1.0f; }

    const int tid  = threadIdx.x;
    const int lane = tid & 31;
    const int wid  = tid >> 5;
    const int g = lane >> 2, t = lane & 3;
    const int wm = wid & 3, wn = wid >> 2;
    const int row0 = rowbase + blockIdx.y * 128;
    const int col0 = blockIdx.x * 128;
    const unsigned sb = smem_u32(smp);

    // staging maps
    const int aArow[4] = { (tid+0)>>3, (tid+256)>>3, (tid+512)>>3, (tid+768)>>3 };
    const int aAc4 = (tid & 7) * 4;
    const int aBkk[4] = { (tid+0)>>5, (tid+256)>>5, (tid+512)>>5, (tid+768)>>5 };
    const int aBn4 = (tid & 31) * 4;

    // ldmatrix lane addresses for A fragments (buffer-0 base)
    const int mrow = lane & 15;
    const int mcol = (lane >> 4) * 4;
    unsigned aaddr[2];
    #pragma unroll
    for (int i = 0; i < 2; i++)
        aaddr[i] = sb + (unsigned)((wm*32 + 16*i + mrow)*PA_STR + mcol)*4;

    float acc[2][8][4];
    #pragma unroll
    for (int i = 0; i < 2; i++)
        #pragma unroll
        for (int j = 0; j < 8; j++)
            #pragma unroll
            for (int r = 0; r < 4; r++) acc[i][j][r] = 0.f;

    // prologue: A chunk0 -> regs; W chunk0 -> sB0 via cp.async
    float4 areg[4];
    #pragma unroll
    for (int u = 0; u < 4; u++) {
        areg[u] = *(const float4*)(A + (size_t)(row0 + aArow[u]) * DM + aAc4);
        cpa16(sb + (unsigned)(2*SA_SZ + aBkk[u]*PB_STR + aBn4) * 4,
              W + (size_t)aBkk[u] * OD + col0 + aBn4);
    }
    CP_COMMIT();

    for (int c = 0; c < DM/32; c++) {
        const int buf = c & 1;
        unsigned* sA = smp + buf * SA_SZ;
        const unsigned* sB = smp + 2*SA_SZ + buf * SB_SZ;
        const unsigned abufofs = (unsigned)(buf * SA_SZ) * 4;

        // stage A chunk c (cvt) into sA[buf]
        #pragma unroll
        for (int u = 0; u < 4; u++)
            *(uint4*)&sA[aArow[u]*PA_STR + aAc4] =
                make_uint4(ftf(areg[u].x), ftf(areg[u].y), ftf(areg[u].z), ftf(areg[u].w));
        // prefetch A chunk c+1
        if (c + 1 < DM/32) {
            #pragma unroll
            for (int u = 0; u < 4; u++)
                areg[u] = *(const float4*)(A + (size_t)(row0 + aArow[u]) * DM
                                             + (c+1)*32 + aAc4);
        }
        CP_WAIT0();
        __syncthreads();
        // issue W chunk c+1 into other buffer
        if (c + 1 < DM/32) {
            unsigned wdst = sb + (unsigned)(2*SA_SZ + (buf^1) * SB_SZ) * 4;
            #pragma unroll
            for (int u = 0; u < 4; u++)
                cpa16(wdst + (unsigned)(aBkk[u]*PB_STR + aBn4) * 4,
                      W + (size_t)((c+1)*32 + aBkk[u]) * OD + col0 + aBn4);
            CP_COMMIT();
        }

        #pragma unroll
        for (int ks = 0; ks < 4; ks++) {
            unsigned a[2][4], b[8][2];
            #pragma unroll
            for (int i = 0; i < 2; i++)
                ldsm4(a[i], aaddr[i] + abufofs + ks * 32);
            #pragma unroll
            for (int j = 0; j < 8; j++) {
                const unsigned* p = &sB[(ks*8 + t)*PB_STR + wn*64 + 8*j + g];
                b[j][0] = p[0];
                b[j][1] = p[4*PB_STR];
            }
            #pragma unroll
            for (int i = 0; i < 2; i++)
                #pragma unroll
                for (int j = 0; j < 8; j++)
                    mma8(acc[i][j], a[i], b[j]);
        }
    }

    // epilogue: scale (Q only) then tf32-round
    #pragma unroll
    for (int i = 0; i < 2; i++) {
        int row = row0 + wm*32 + 16*i + g;
        #pragma unroll
        for (int j = 0; j < 8; j++) {
            int col = col0 + wn*64 + 8*j + 2*t;
            *(float2*)(C + (size_t)row * OD + col) =
                make_float2(ftff(acc[i][j][0] * osc), ftff(acc[i][j][1] * osc));
            *(float2*)(C + (size_t)(row+8) * OD + col) =
                make_float2(ftff(acc[i][j][2] * osc), ftff(acc[i][j][3] * osc));
        }
    }
}

// ===========================================================================
// Attention (R11 frozen, batch passed as arg): CTA = (h, 128 q rows).
// K/V/bias via cp.async double-buffered pipeline; Q frags hoisted to regs.
// log2-domain softmax, bare ex2. Shuffle-based P conversion.
// smem words: Q[128][68], K[2][64][68], V[2][64][72], bias[2][64].
// ===========================================================================
#define QST 68
#define KST 68
#define VST 72
#define QOF 0
#define KOF (128*QST)          // 8704
#define KBUF (64*KST)          // 4352
#define VOF (KOF + 2*KBUF)     // 17408
#define VBUF (64*VST)          // 4608
#define BOF (VOF + 2*VBUF)     // 26624
#define AS_WORDS (BOF + 128)   // 26752
#define AS_BYTES (AS_WORDS*4)  // 107008
#define NKT (SEQ/64)           // 32

__global__ void __launch_bounds__(128, 2) attn_tc(
    const float* __restrict__ qmask, float* __restrict__ out, int b)
{
    extern __shared__ unsigned sm[];
    float* smF = (float*)sm;
    const int tid  = threadIdx.x;
    const int lane = tid & 31;
    const int w    = tid >> 5;
    const int g = lane >> 2, t = lane & 3;
    const int h  = blockIdx.y;
    const int q0 = blockIdx.x * 128;
    const unsigned sb = smem_u32(sm);

    // staging maps (128 threads; K/V tile 64x64 -> 8 chunks, Q 128x64 -> 16)
    const int srow[8] = { (tid+0)>>4, (tid+128)>>4, (tid+256)>>4, (tid+384)>>4,
                          (tid+512)>>4, (tid+640)>>4, (tid+768)>>4, (tid+896)>>4 };
    const int sc4 = (tid & 15) * 4;

    // ---- prologue: Q + tile0 K/V/bias via cp.async (one group) ----
    {
        const float* Qg = g_qw + (size_t)(b*SEQ + q0) * OD + h*HD;
        #pragma unroll
        for (int u = 0; u < 16; u++) {
            int idx = tid + 128*u;
            int row = idx >> 4;
            cpa16(sb + (unsigned)(QOF + row*QST + sc4)*4, Qg + (size_t)row*OD + sc4);
        }
        const float* Kg = g_kw + (size_t)(b*SEQ) * OD + h*HD;
        const float* Vg = g_vw + (size_t)(b*SEQ) * OD + h*HD;
        #pragma unroll
        for (int u = 0; u < 8; u++) {
            cpa16(sb + (unsigned)(KOF + srow[u]*KST + sc4)*4, Kg + (size_t)srow[u]*OD + sc4);
            cpa16(sb + (unsigned)(VOF + srow[u]*VST + sc4)*4, Vg + (size_t)srow[u]*OD + sc4);
        }
        if (tid < 16)
            cpa16(sb + (unsigned)(BOF + tid*4)*4, g_bias + (size_t)b*SEQ + tid*4);
        CP_COMMIT();
    }

    // ---- ldmatrix lane addresses ----
    const int mrow = lane & 15;
    const int mcol = (lane >> 4) * 4;
    unsigned kaddr0[4];
    #pragma unroll
    for (int jp = 0; jp < 4; jp++)
        kaddr0[jp] = sb + (unsigned)(KOF + (jp*16 + mrow)*KST + mcol)*4;

    // ---- wait for prologue, then hoist Q fragments into registers ----
    CP_WAIT0();
    __syncthreads();
    unsigned qa[2][8][4];
    {
        unsigned qaddr0 = sb + (unsigned)(QOF + (w*32 + mrow)*QST + mcol)*4;
        unsigned qaddr1 = sb + (unsigned)(QOF + (w*32 + 16 + mrow)*QST + mcol)*4;
        #pragma unroll
        for (int ks = 0; ks < 8; ks++) {
            ldsm4(qa[0][ks], qaddr0 + ks*32);
            ldsm4(qa[1][ks], qaddr1 + ks*32);
        }
    }

    float o[2][8][4];
    #pragma unroll
    for (int i = 0; i < 2; i++)
        #pragma unroll
        for (int j = 0; j < 8; j++)
            #pragma unroll
            for (int r = 0; r < 4; r++) o[i][j][r] = 0.f;
    float l[2][2] = {{0.f, 0.f}, {0.f, 0.f}};

    for (int kt = 0; kt < NKT; kt++) {
        const int buf = kt & 1;
        if (kt > 0) {
            CP_WAIT0();
            __syncthreads();
        }

        // issue K/V/bias for kt+1 into the other buffer (overlaps compute)
        if (kt + 1 < NKT) {
            const int k1 = (kt + 1) * 64;
            const float* Kg = g_kw + (size_t)(b*SEQ + k1) * OD + h*HD;
            const float* Vg = g_vw + (size_t)(b*SEQ + k1) * OD + h*HD;
            unsigned kdst = sb + (unsigned)(KOF + (buf^1)*KBUF)*4;
            unsigned vdst = sb + (unsigned)(VOF + (buf^1)*VBUF)*4;
            #pragma unroll
            for (int u = 0; u < 8; u++) {
                cpa16(kdst + (unsigned)(srow[u]*KST + sc4)*4, Kg + (size_t)srow[u]*OD + sc4);
                cpa16(vdst + (unsigned)(srow[u]*VST + sc4)*4, Vg + (size_t)srow[u]*OD + sc4);
            }
            if (tid < 16)
                cpa16(sb + (unsigned)(BOF + (buf^1)*64 + tid*4)*4,
                      g_bias + (size_t)b*SEQ + k1 + tid*4);
            CP_COMMIT();
        }

        const unsigned kofs = (unsigned)(buf * KBUF) * 4;
        const int vbase = VOF + buf * VBUF;
        const int bbase = BOF + buf * 64;

        // ---- S' = (Q*log2e/8) K^T : warp tile 32 x 64, Q from registers ----
        float s[2][8][4];
        #pragma unroll
        for (int i = 0; i < 2; i++)
            #pragma unroll
            for (int j = 0; j < 8; j++)
                #pragma unroll
                for (int r = 0; r < 4; r++) s[i][j][r] = 0.f;

        #pragma unroll
        for (int ks = 0; ks < 8; ks++) {
            unsigned bb[4][4];
            #pragma unroll
            for (int jp = 0; jp < 4; jp++) ldsm4(bb[jp], kaddr0[jp] + kofs + ks*32);
            #pragma unroll
            for (int j = 0; j < 8; j++) {
                unsigned bfr[2] = { bb[j>>1][j&1], bb[j>>1][2+(j&1)] };
                mma8(s[0][j], qa[0][ks], bfr);
                mma8(s[1][j], qa[1][ks], bfr);
            }
        }

        // ---- p = 2^(s' - bias'), accumulate row sums ----
        #pragma unroll
        for (int j = 0; j < 8; j++) {
            float bl = smF[bbase + 8*j + 2*t];
            float bh = smF[bbase + 8*j + 2*t + 1];
            #pragma unroll
            for (int i = 0; i < 2; i++) {
                float p0 = ex2(s[i][j][0] - bl);
                float p1 = ex2(s[i][j][1] - bh);
                float p2 = ex2(s[i][j][2] - bl);
                float p3 = ex2(s[i][j][3] - bh);
                l[i][0] += p0 + p1;
                l[i][1] += p2 + p3;
                s[i][j][0] = p0; s[i][j][1] = p1; s[i][j][2] = p2; s[i][j][3] = p3;
            }
        }

        // ---- O += P V : P A-frags via intra-quad shuffles ----
        const int srcl = (lane & ~3) | (t >> 1);
        const bool odd = (t & 1);
        #pragma unroll
        for (int ks = 0; ks < 8; ks++) {
            unsigned a[2][4];
            #pragma unroll
            for (int i = 0; i < 2; i++) {
                float v00 = __shfl_sync(0xffffffffu, s[i][ks][0], srcl);
                float v01 = __shfl_sync(0xffffffffu, s[i][ks][1], srcl);
                float v10 = __shfl_sync(0xffffffffu, s[i][ks][2], srcl);
                float v11 = __shfl_sync(0xffffffffu, s[i][ks][3], srcl);
                float v20 = __shfl_sync(0xffffffffu, s[i][ks][0], srcl + 2);
                float v21 = __shfl_sync(0xffffffffu, s[i][ks][1], srcl + 2);
                float v30 = __shfl_sync(0xffffffffu, s[i][ks][2], srcl + 2);
                float v31 = __shfl_sync(0xffffffffu, s[i][ks][3], srcl + 2);
                a[i][0] = ftf(odd ? v01 : v00);
                a[i][1] = ftf(odd ? v11 : v10);
                a[i][2] = ftf(odd ? v21 : v20);
                a[i][3] = ftf(odd ? v31 : v30);
            }
            #pragma unroll
            for (int j = 0; j < 8; j++) {
                unsigned bfr[2];
                bfr[0] = sm[vbase + (ks*8 + t)*VST + 8*j + g];
                bfr[1] = sm[vbase + (ks*8 + t + 4)*VST + 8*j + g];
                mma8(o[0][j], a[0], bfr);
                mma8(o[1][j], a[1], bfr);
            }
        }
    }

    // ---- epilogue: reduce l over quad lanes, normalize, q_mask, store ----
    #pragma unroll
    for (int i = 0; i < 2; i++) {
        l[i][0] += __shfl_xor_sync(0xffffffffu, l[i][0], 1);
        l[i][0] += __shfl_xor_sync(0xffffffffu, l[i][0], 2);
        l[i][1] += __shfl_xor_sync(0xffffffffu, l[i][1], 1);
        l[i][1] += __shfl_xor_sync(0xffffffffu, l[i][1], 2);
    }
    float* O = out + (size_t)(b*SEQ + q0) * OD + h*HD;
    #pragma unroll
    for (int i = 0; i < 2; i++) {
        int r0 = w*32 + 16*i + g;
        float f0 = qmask[(size_t)b*SEQ + q0 + r0] / l[i][0];
        float f1 = qmask[(size_t)b*SEQ + q0 + r0 + 8] / l[i][1];
        #pragma unroll
        for (int j = 0; j < 8; j++) {
            int col = 8*j + 2*t;
            *(float2*)(O + (size_t)r0 * OD + col) =
                make_float2(o[i][j][0] * f0, o[i][j][1] * f0);
            *(float2*)(O + (size_t)(r0+8) * OD + col) =
                make_float2(o[i][j][2] * f1, o[i][j][3] * f1);
        }
    }
}

// ===========================================================================
extern "C" void kernel_launch(void* const* d_in, const int* in_sizes, int n_in,
                              void* d_out, int out_size)
{
    const float* q     = (const float*)d_in[0];
    const float* k     = (const float*)d_in[1];
    const float* v     = (const float*)d_in[2];
    const float* vmask = (const float*)d_in[3];
    const float* qmask = (const float*)d_in[4];
    const float* wq    = (const float*)d_in[5];
    const float* wk    = (const float*)d_in[6];
    const float* wv    = (const float*)d_in[7];
    float* out = (float*)d_out;

    // one-time stream/event setup (first call is the uncaptured correctness
    // run; subsequent captured calls issue identical work every time)
    static cudaStream_t s2 = nullptr;
    static cudaEvent_t evP = nullptr, ev2 = nullptr;
    if (s2 == nullptr) {
        cudaStreamCreateWithFlags(&s2, cudaStreamNonBlocking);
        cudaEventCreateWithFlags(&evP, cudaEventDisableTiming);
        cudaEventCreateWithFlags(&ev2, cudaEventDisableTiming);
        cudaFuncSetAttribute(proj_tc, cudaFuncAttributeMaxDynamicSharedMemorySize, PS_BYTES);
        cudaFuncSetAttribute(attn_tc, cudaFuncAttributeMaxDynamicSharedMemorySize, AS_BYTES);
    }

    dim3 gg(1024, 4);
    prepass<<<gg, 256>>>(wq, wk, wv, vmask);
    cudaEventRecord(evP, 0);

    // pipeline for batch 1 on stream s2 (depends only on prepass)
    cudaStreamWaitEvent(s2, evP, 0);
    dim3 pg(OD / 128, SEQ / 128, 3);      // 8 x 16 x 3 per batch half
    proj_tc<<<pg, 256, PS_BYTES, s2>>>(q, k, v, SEQ);
    dim3 ag(SEQ / 128, NH);               // 16 x 16 per batch
    attn_tc<<<ag, 128, AS_BYTES, s2>>>(qmask, out, 1);
    cudaEventRecord(ev2, s2);

    // pipeline for batch 0 on the main (capture) stream
    proj_tc<<<pg, 256, PS_BYTES>>>(q, k, v, 0);
    attn_tc<<<ag, 128, AS_BYTES>>>(qmask, out, 0);

    // join
    cudaStreamWaitEvent(0, ev2, 0);
}